// round 1
// baseline (speedup 1.0000x reference)
#include <cuda_runtime.h>
#include <cuda_bf16.h>
#include <math.h>

// ---------------- Problem constants ----------------
#define S 2048
#define H 2048
#define NH 16
#define NOPE 128
#define ROPE 64
#define VHD 128
#define QHD 192          // NOPE + ROPE
#define QLR 1536
#define KVLR 512
#define FF 8192
#define CKV_N 576        // KVLR + ROPE
#define QDIM (NH*QHD)    // 3072
#define KVDIM (NH*(NOPE+VHD)) // 4096
#define ATTN_SCALE 0.07216878364870323f  // 1/sqrt(192)

// ---------------- Scratch (device globals; no allocation allowed) ----------
__device__ float g_x[S*H];
__device__ float g_qlat[S*QLR];
__device__ float g_qlatn[S*QLR];
__device__ float g_q[S*QDIM];
__device__ float g_ckv[S*CKV_N];
__device__ float g_ckvn[S*KVLR];
__device__ float g_kv[S*KVDIM];
__device__ float g_kpe[S*ROPE];
__device__ float g_attn[S*H];
__device__ float g_hidden[S*H];
__device__ float g_y[S*H];
__device__ float g_gate[S*FF];
__device__ float g_up[S*FF];

// ---------------- RMSNorm: one block per row ----------------
__global__ void rmsnorm_kernel(const float* __restrict__ in, const float* __restrict__ w,
                               float* __restrict__ out, int N, int ldin, int ldout) {
    int row = blockIdx.x;
    const float* x = in + (size_t)row * ldin;
    __shared__ float red[256];
    float s = 0.f;
    for (int i = threadIdx.x; i < N; i += 256) { float v = x[i]; s += v * v; }
    red[threadIdx.x] = s;
    __syncthreads();
    for (int o = 128; o > 0; o >>= 1) {
        if (threadIdx.x < o) red[threadIdx.x] += red[threadIdx.x + o];
        __syncthreads();
    }
    float scale = rsqrtf(red[0] / (float)N + 1e-6f);
    float* op = out + (size_t)row * ldout;
    for (int i = threadIdx.x; i < N; i += 256) op[i] = x[i] * scale * w[i];
}

// ---------------- SGEMM: C[M,N] = A[M,K]*B[K,N] (+C0), 128x128x8, 8x8/thread --
#define BM 128
#define BN 128
#define BK 8
__global__ __launch_bounds__(256) void sgemm_kernel(
    const float* __restrict__ A, const float* __restrict__ B,
    const float* __restrict__ C0, float* __restrict__ C,
    int M, int N, int K, int addC) {
    __shared__ float As[BK][BM + 4];
    __shared__ float Bs[BK][BN + 4];
    int tid = threadIdx.x;
    int tx = tid & 15, ty = tid >> 4;
    int brow = blockIdx.y * BM, bcol = blockIdx.x * BN;

    float acc[8][8];
    #pragma unroll
    for (int i = 0; i < 8; ++i)
        #pragma unroll
        for (int j = 0; j < 8; ++j) acc[i][j] = 0.f;

    int arow = tid >> 1;          // 0..127
    int akq  = (tid & 1) * 4;     // 0 or 4
    int bkr  = tid >> 5;          // 0..7
    int bc   = (tid & 31) * 4;    // 0..124
    const float* Aptr = A + (size_t)(brow + arow) * K + akq;
    const float* Bptr = B + (size_t)bkr * N + bcol + bc;
    bool bvalid = (bcol + bc) < N;   // N % 4 == 0 always here

    for (int k0 = 0; k0 < K; k0 += BK) {
        float4 av = *(const float4*)(Aptr + k0);
        float4 bv = bvalid ? *(const float4*)(Bptr + (size_t)k0 * N)
                           : make_float4(0.f, 0.f, 0.f, 0.f);
        As[akq + 0][arow] = av.x; As[akq + 1][arow] = av.y;
        As[akq + 2][arow] = av.z; As[akq + 3][arow] = av.w;
        *(float4*)&Bs[bkr][bc] = bv;
        __syncthreads();
        #pragma unroll
        for (int k = 0; k < BK; ++k) {
            float a[8], b[8];
            *(float4*)(a)     = *(const float4*)&As[k][ty * 8];
            *(float4*)(a + 4) = *(const float4*)&As[k][ty * 8 + 4];
            *(float4*)(b)     = *(const float4*)&Bs[k][tx * 8];
            *(float4*)(b + 4) = *(const float4*)&Bs[k][tx * 8 + 4];
            #pragma unroll
            for (int i = 0; i < 8; ++i)
                #pragma unroll
                for (int j = 0; j < 8; ++j)
                    acc[i][j] = fmaf(a[i], b[j], acc[i][j]);
        }
        __syncthreads();
    }

    #pragma unroll
    for (int i = 0; i < 8; ++i) {
        int gr = brow + ty * 8 + i;
        #pragma unroll
        for (int j = 0; j < 8; ++j) {
            int gc = bcol + tx * 8 + j;
            if (gr < M && gc < N) {
                float v = acc[i][j];
                if (addC) v += C0[(size_t)gr * N + gc];
                C[(size_t)gr * N + gc] = v;
            }
        }
    }
}

// ---------------- RoPE (interleaved): q pe part in-place, ckv rope -> kpe ----
__global__ void rope_kernel(float* __restrict__ q, const float* __restrict__ ckv,
                            float* __restrict__ kpe,
                            const float* __restrict__ cosb, const float* __restrict__ sinb,
                            const int* __restrict__ pos) {
    int s = blockIdx.x;
    int p = pos[s];
    const float* c  = cosb + (size_t)p * ROPE;
    const float* sn = sinb + (size_t)p * ROPE;
    int idx = threadIdx.x;
    if (idx < NH * 32) {             // one warp per head (32 rotation pairs)
        int h = idx >> 5, j = idx & 31;
        float* qp = q + (size_t)s * QDIM + h * QHD + NOPE;
        float x0 = qp[2 * j], x1 = qp[2 * j + 1];
        __syncwarp();
        qp[j]      = x0 * c[j]      - x1 * sn[j];
        qp[j + 32] = x1 * c[j + 32] + x0 * sn[j + 32];
    } else if (idx < NH * 32 + 32) { // k_pe: 32 pairs (one warp)
        int j = idx - NH * 32;
        const float* kp = ckv + (size_t)s * CKV_N + KVLR;
        float x0 = kp[2 * j], x1 = kp[2 * j + 1];
        kpe[(size_t)s * ROPE + j]      = x0 * c[j]      - x1 * sn[j];
        kpe[(size_t)s * ROPE + j + 32] = x1 * c[j + 32] + x0 * sn[j + 32];
    }
}

// ---------------- Causal flash attention (fp32, online softmax) -------------
// grid: (S/64 q-tiles, NH heads), 256 threads. BM=BN=64, D=192, DV=128.
#define FBM 64
#define FBN 64
__global__ __launch_bounds__(256) void flash_kernel(
    const float* __restrict__ q, const float* __restrict__ kv,
    const float* __restrict__ kpe, float* __restrict__ attn) {
    __shared__ float Qs[16][FBM + 4];
    __shared__ float Ks[16][FBN + 4];
    __shared__ float Vs[16][VHD + 4];
    __shared__ float Ssm[FBM][FBN + 4];
    __shared__ float m_s[FBM], l_s[FBM], fac_s[FBM];

    int qbase = blockIdx.x * FBM;
    int h = blockIdx.y;
    int tid = threadIdx.x;
    int tx = tid & 15, ty = tid >> 4;

    float oacc[4][8];
    #pragma unroll
    for (int i = 0; i < 4; ++i)
        #pragma unroll
        for (int c = 0; c < 8; ++c) oacc[i][c] = 0.f;
    if (tid < FBM) { m_s[tid] = -1e30f; l_s[tid] = 0.f; }

    int qm = tid & 63;            // staging row
    int qk = (tid >> 6) << 2;     // staging k offset (0,4,8,12)
    int vk = tid >> 4;            // V staging k-row
    int vc = (tid & 15) * 8;      // V staging col

    int ntiles = (qbase / FBN) + 1;
    for (int jt = 0; jt < ntiles; ++jt) {
        int kbase = jt * FBN;
        float sacc[4][4];
        #pragma unroll
        for (int i = 0; i < 4; ++i)
            #pragma unroll
            for (int j = 0; j < 4; ++j) sacc[i][j] = 0.f;

        // --- scores = Q * K^T over D=192, chunks of 16 ---
        for (int kc = 0; kc < QHD; kc += 16) {
            __syncthreads();
            float4 qv = *(const float4*)(q + (size_t)(qbase + qm) * QDIM + h * QHD + kc + qk);
            Qs[qk + 0][qm] = qv.x; Qs[qk + 1][qm] = qv.y;
            Qs[qk + 2][qm] = qv.z; Qs[qk + 3][qm] = qv.w;
            float4 kvv;
            if (kc < NOPE)
                kvv = *(const float4*)(kv + (size_t)(kbase + qm) * KVDIM + h * (NOPE + VHD) + kc + qk);
            else
                kvv = *(const float4*)(kpe + (size_t)(kbase + qm) * ROPE + (kc - NOPE) + qk);
            Ks[qk + 0][qm] = kvv.x; Ks[qk + 1][qm] = kvv.y;
            Ks[qk + 2][qm] = kvv.z; Ks[qk + 3][qm] = kvv.w;
            __syncthreads();
            #pragma unroll
            for (int k = 0; k < 16; ++k) {
                float a[4], b[4];
                *(float4*)a = *(const float4*)&Qs[k][ty * 4];
                *(float4*)b = *(const float4*)&Ks[k][tx * 4];
                #pragma unroll
                for (int i = 0; i < 4; ++i)
                    #pragma unroll
                    for (int j = 0; j < 4; ++j)
                        sacc[i][j] = fmaf(a[i], b[j], sacc[i][j]);
            }
        }

        // --- scale + causal mask, write to smem ---
        #pragma unroll
        for (int i = 0; i < 4; ++i) {
            int gr = qbase + ty * 4 + i;
            #pragma unroll
            for (int j = 0; j < 4; ++j) {
                int gc = kbase + tx * 4 + j;
                float v = sacc[i][j] * ATTN_SCALE;
                if (gc > gr) v = -1e30f;
                Ssm[ty * 4 + i][tx * 4 + j] = v;
            }
        }
        __syncthreads();

        // --- online softmax, one thread per row ---
        if (tid < FBM) {
            float mx = -1e30f;
            for (int c = 0; c < FBN; ++c) mx = fmaxf(mx, Ssm[tid][c]);
            float nm = fmaxf(m_s[tid], mx);
            float f = __expf(m_s[tid] - nm);
            float ps = 0.f;
            for (int c = 0; c < FBN; ++c) {
                float pv = __expf(Ssm[tid][c] - nm);
                Ssm[tid][c] = pv;
                ps += pv;
            }
            l_s[tid] = l_s[tid] * f + ps;
            m_s[tid] = nm;
            fac_s[tid] = f;
        }
        __syncthreads();

        // --- rescale accumulators ---
        #pragma unroll
        for (int i = 0; i < 4; ++i) {
            float f = fac_s[ty * 4 + i];
            #pragma unroll
            for (int c = 0; c < 8; ++c) oacc[i][c] *= f;
        }

        // --- O += P * V, key chunks of 16 ---
        for (int vcc = 0; vcc < FBN; vcc += 16) {
            __syncthreads();
            const float* vptr = kv + (size_t)(kbase + vcc + vk) * KVDIM + h * (NOPE + VHD) + NOPE + vc;
            *(float4*)&Vs[vk][vc]     = *(const float4*)(vptr);
            *(float4*)&Vs[vk][vc + 4] = *(const float4*)(vptr + 4);
            __syncthreads();
            #pragma unroll
            for (int k = 0; k < 16; ++k) {
                float b[8];
                *(float4*)(b)     = *(const float4*)&Vs[k][tx * 8];
                *(float4*)(b + 4) = *(const float4*)&Vs[k][tx * 8 + 4];
                #pragma unroll
                for (int i = 0; i < 4; ++i) {
                    float pv = Ssm[ty * 4 + i][vcc + k];
                    #pragma unroll
                    for (int c = 0; c < 8; ++c)
                        oacc[i][c] = fmaf(pv, b[c], oacc[i][c]);
                }
            }
        }
    }

    // --- epilogue: normalize and write [s, h*128 + col] ---
    #pragma unroll
    for (int i = 0; i < 4; ++i) {
        int gr = qbase + ty * 4 + i;
        float inv = 1.f / l_s[ty * 4 + i];
        #pragma unroll
        for (int c = 0; c < 8; ++c)
            attn[(size_t)gr * H + h * VHD + tx * 8 + c] = oacc[i][c] * inv;
    }
}

// ---------------- SiLU(gate) * up, in place into gate -----------------------
__global__ void silu_mul_kernel(float* __restrict__ gate, const float* __restrict__ up, int n4) {
    int i = blockIdx.x * blockDim.x + threadIdx.x;
    if (i < n4) {
        float4 g = ((const float4*)gate)[i];
        float4 u = ((const float4*)up)[i];
        g.x = (g.x / (1.f + __expf(-g.x))) * u.x;
        g.y = (g.y / (1.f + __expf(-g.y))) * u.y;
        g.z = (g.z / (1.f + __expf(-g.z))) * u.z;
        g.w = (g.w / (1.f + __expf(-g.w))) * u.w;
        ((float4*)gate)[i] = g;
    }
}

// ---------------- Launch ----------------------------------------------------
static inline dim3 gemm_grid(int M, int N) {
    return dim3((N + BN - 1) / BN, (M + BM - 1) / BM);
}

extern "C" void kernel_launch(void* const* d_in, const int* in_sizes, int n_in,
                              void* d_out, int out_size) {
    const float* hs      = (const float*)d_in[0];
    const float* sinb    = (const float*)d_in[1];
    const float* cosb    = (const float*)d_in[2];
    const float* wq_a    = (const float*)d_in[3];
    const float* q_a_ln  = (const float*)d_in[4];
    const float* wq_b    = (const float*)d_in[5];
    const float* wkv_a   = (const float*)d_in[6];
    const float* kv_a_ln = (const float*)d_in[7];
    const float* wkv_b   = (const float*)d_in[8];
    const float* wo      = (const float*)d_in[9];
    const float* in_ln   = (const float*)d_in[10];
    const float* post_ln = (const float*)d_in[11];
    const float* w_gate  = (const float*)d_in[12];
    const float* w_up    = (const float*)d_in[13];
    const float* w_down  = (const float*)d_in[14];
    const int*   pos     = (const int*)d_in[15];
    float* out = (float*)d_out;

    float *x, *qlat, *qlatn, *qb, *ckv, *ckvn, *kvb, *kpe, *attn, *hidden, *y, *gate, *up;
    cudaGetSymbolAddress((void**)&x,      g_x);
    cudaGetSymbolAddress((void**)&qlat,   g_qlat);
    cudaGetSymbolAddress((void**)&qlatn,  g_qlatn);
    cudaGetSymbolAddress((void**)&qb,     g_q);
    cudaGetSymbolAddress((void**)&ckv,    g_ckv);
    cudaGetSymbolAddress((void**)&ckvn,   g_ckvn);
    cudaGetSymbolAddress((void**)&kvb,    g_kv);
    cudaGetSymbolAddress((void**)&kpe,    g_kpe);
    cudaGetSymbolAddress((void**)&attn,   g_attn);
    cudaGetSymbolAddress((void**)&hidden, g_hidden);
    cudaGetSymbolAddress((void**)&y,      g_y);
    cudaGetSymbolAddress((void**)&gate,   g_gate);
    cudaGetSymbolAddress((void**)&up,     g_up);

    // 1. x = rms(hidden_states, in_ln)
    rmsnorm_kernel<<<S, 256>>>(hs, in_ln, x, H, H, H);
    // 2. q_lat = x @ wq_a ; normalize ; q = q_lat_n @ wq_b
    sgemm_kernel<<<gemm_grid(S, QLR), 256>>>(x, wq_a, nullptr, qlat, S, QLR, H, 0);
    rmsnorm_kernel<<<S, 256>>>(qlat, q_a_ln, qlatn, QLR, QLR, QLR);
    sgemm_kernel<<<gemm_grid(S, QDIM), 256>>>(qlatn, wq_b, nullptr, qb, S, QDIM, QLR, 0);
    // 3. ckv = x @ wkv_a ; normalize first 512 ; kv = ckv_n @ wkv_b
    sgemm_kernel<<<gemm_grid(S, CKV_N), 256>>>(x, wkv_a, nullptr, ckv, S, CKV_N, H, 0);
    rmsnorm_kernel<<<S, 256>>>(ckv, kv_a_ln, ckvn, KVLR, CKV_N, KVLR);
    sgemm_kernel<<<gemm_grid(S, KVDIM), 256>>>(ckvn, wkv_b, nullptr, kvb, S, KVDIM, KVLR, 0);
    // 4. rope: q pe in place, k_pe -> kpe
    rope_kernel<<<S, 576>>>(qb, ckv, kpe, cosb, sinb, pos);
    // 5. causal attention -> attn [S, NH*128]
    flash_kernel<<<dim3(S / FBM, NH), 256>>>(qb, kvb, kpe, attn);
    // 6. hidden = hidden_states + attn @ wo
    sgemm_kernel<<<gemm_grid(S, H), 256>>>(attn, wo, hs, hidden, S, H, H, 1);
    // 7. y = rms(hidden, post_ln)
    rmsnorm_kernel<<<S, 256>>>(hidden, post_ln, y, H, H, H);
    // 8. MLP
    sgemm_kernel<<<gemm_grid(S, FF), 256>>>(y, w_gate, nullptr, gate, S, FF, H, 0);
    sgemm_kernel<<<gemm_grid(S, FF), 256>>>(y, w_up, nullptr, up, S, FF, H, 0);
    int n4 = S * FF / 4;
    silu_mul_kernel<<<(n4 + 255) / 256, 256>>>(gate, up, n4);
    // 9. out = hidden + act @ w_down
    sgemm_kernel<<<gemm_grid(S, H), 256>>>(gate, w_down, hidden, out, S, H, FF, 1);
}

// round 16
// speedup vs baseline: 2.5572x; 2.5572x over previous
#include <cuda_runtime.h>
#include <cuda_bf16.h>
#include <stdint.h>
#include <cstdint>
#include <math.h>

// ---------------- Problem constants ----------------
#define S 2048
#define H 2048
#define NH 16
#define NOPE 128
#define ROPE 64
#define VHD 128
#define QHD 192          // NOPE + ROPE
#define QLR 1536
#define KVLR 512
#define FF 8192
#define CKV_N 576        // KVLR + ROPE
#define QDIM (NH*QHD)    // 3072
#define KVDIM (NH*(NOPE+VHD)) // 4096
#define ATTN_SCALE 0.07216878364870323f  // 1/sqrt(192)

// ---------------- Scratch (device globals; no allocation allowed) ----------
__device__ float g_x[S*H];
__device__ float g_qlat[S*QLR];
__device__ float g_qlatn[S*QLR];
__device__ float g_q[S*QDIM];
__device__ float g_ckv[S*CKV_N];
__device__ float g_ckvn[S*KVLR];
__device__ float g_kv[S*KVDIM];
__device__ float g_kpe[S*ROPE];
__device__ float g_attn[S*H];
__device__ float g_hidden[S*H];
__device__ float g_y[S*H];
__device__ float g_gate[S*FF];
__device__ float g_up[S*FF];

__device__ __forceinline__ void mma_tf32(float* d, const uint32_t* a, const uint32_t* b) {
    asm volatile(
        "mma.sync.aligned.m16n8k8.row.col.f32.tf32.tf32.f32 "
        "{%0,%1,%2,%3}, {%4,%5,%6,%7}, {%8,%9}, {%0,%1,%2,%3};"
        : "+f"(d[0]), "+f"(d[1]), "+f"(d[2]), "+f"(d[3])
        : "r"(a[0]), "r"(a[1]), "r"(a[2]), "r"(a[3]), "r"(b[0]), "r"(b[1]));
}

// Round-to-nearest tf32 quantization (unbiased) -> bit pattern for mma.
__device__ __forceinline__ uint32_t tf32_rna(float x) {
    uint32_t u;
    asm("cvt.rna.tf32.f32 %0, %1;" : "=r"(u) : "f"(x));
    return u;
}

// 16B async copy GMEM->SMEM; pred=false zero-fills the 16 bytes.
__device__ __forceinline__ void cp_async16(float* smem, const float* gmem, bool pred) {
    uint32_t s = (uint32_t)__cvta_generic_to_shared(smem);
    int sz = pred ? 16 : 0;
    asm volatile("cp.async.ca.shared.global [%0], [%1], 16, %2;"
                 :: "r"(s), "l"(gmem), "r"(sz));
}

// ---------------- RMSNorm: one block per row ----------------
__global__ void rmsnorm_kernel(const float* __restrict__ in, const float* __restrict__ w,
                               float* __restrict__ out, int N, int ldin, int ldout) {
    int row = blockIdx.x;
    const float* x = in + (size_t)row * ldin;
    __shared__ float red[256];
    float s = 0.f;
    for (int i = threadIdx.x; i < N; i += 256) { float v = x[i]; s += v * v; }
    red[threadIdx.x] = s;
    __syncthreads();
    for (int o = 128; o > 0; o >>= 1) {
        if (threadIdx.x < o) red[threadIdx.x] += red[threadIdx.x + o];
        __syncthreads();
    }
    float scale = rsqrtf(red[0] / (float)N + 1e-6f);
    float* op = out + (size_t)row * ldout;
    for (int i = threadIdx.x; i < N; i += 256) op[i] = x[i] * scale * w[i];
}

// ---------------- TF32 tensor-core GEMM: C[M,N] = A[M,K]*B[K,N] (+C0) -------
// 128x128x16 tiles, 256 threads (8 warps), warp tile 64x32 (2x4 warp grid).
// mma.sync.m16n8k8 tf32, RNA rounding at fragment load (unbiased).
// cp.async 2-stage double-buffered SMEM pipeline.
#define BM 128
#define BN 128
#define BK 16
__global__ __launch_bounds__(256) void tf32_gemm_kernel(
    const float* __restrict__ A, const float* __restrict__ B,
    const float* __restrict__ C0, float* __restrict__ C,
    int M, int N, int K, int addC) {
    // row strides: As 20 floats = 80B (16B-mult), Bs 136 floats = 544B (16B-mult)
    __shared__ float As[2][BM][BK + 4];
    __shared__ float Bs[2][BK][BN + 8];

    int tid = threadIdx.x;
    int warp = tid >> 5, lane = tid & 31;
    int wm = (warp & 1) * 64;          // warp row offset within tile
    int wn = (warp >> 1) * 32;         // warp col offset within tile
    int brow = blockIdx.y * BM, bcol = blockIdx.x * BN;

    float acc[4][4][4];
    #pragma unroll
    for (int i = 0; i < 4; ++i)
        #pragma unroll
        for (int j = 0; j < 4; ++j)
            #pragma unroll
            for (int f = 0; f < 4; ++f) acc[i][j][f] = 0.f;

    // staging indices
    int arow = tid >> 1;               // 0..127
    int acol = (tid & 1) * 8;          // 0 or 8
    int bkr  = tid >> 5;               // 0..7 (also +8)
    int bcc  = lane * 4;               // 0..124, 16B aligned
    const float* Ag = A + (size_t)(brow + arow) * K + acol;
    const float* Bg = B + (size_t)bkr * N + bcol + bcc;
    bool bvalid = (bcol + bcc) < N;

    int ntile = K / BK;

    auto issue_tile = [&](int buf, int kt) {
        const float* An = Ag + (size_t)kt * BK;
        const float* Bn = bvalid ? (Bg + (size_t)kt * BK * N) : B;
        cp_async16(&As[buf][arow][acol],     An,     true);
        cp_async16(&As[buf][arow][acol + 4], An + 4, true);
        cp_async16(&Bs[buf][bkr][bcc],       Bn,                     bvalid);
        cp_async16(&Bs[buf][bkr + 8][bcc],   Bn + 8 * (size_t)N,     bvalid);
        asm volatile("cp.async.commit_group;" ::: "memory");
    };

    // prologue: stage 0 in flight
    issue_tile(0, 0);

    for (int kt = 0; kt < ntile; ++kt) {
        int buf = kt & 1;
        if (kt + 1 < ntile) {
            issue_tile(buf ^ 1, kt + 1);
            asm volatile("cp.async.wait_group 1;" ::: "memory");
        } else {
            asm volatile("cp.async.wait_group 0;" ::: "memory");
        }
        __syncthreads();

        #pragma unroll
        for (int ks = 0; ks < 2; ++ks) {
            uint32_t afr[4][4], bfr[4][2];
            int r0 = wm + (lane >> 2);
            int c0 = ks * 8 + (lane & 3);
            #pragma unroll
            for (int mt = 0; mt < 4; ++mt) {
                afr[mt][0] = tf32_rna(As[buf][r0 + mt * 16 + 0][c0 + 0]);
                afr[mt][1] = tf32_rna(As[buf][r0 + mt * 16 + 8][c0 + 0]);
                afr[mt][2] = tf32_rna(As[buf][r0 + mt * 16 + 0][c0 + 4]);
                afr[mt][3] = tf32_rna(As[buf][r0 + mt * 16 + 8][c0 + 4]);
            }
            #pragma unroll
            for (int nt = 0; nt < 4; ++nt) {
                int bc0 = wn + nt * 8 + (lane >> 2);
                bfr[nt][0] = tf32_rna(Bs[buf][ks * 8 + (lane & 3) + 0][bc0]);
                bfr[nt][1] = tf32_rna(Bs[buf][ks * 8 + (lane & 3) + 4][bc0]);
            }
            #pragma unroll
            for (int mt = 0; mt < 4; ++mt)
                #pragma unroll
                for (int nt = 0; nt < 4; ++nt)
                    mma_tf32(acc[mt][nt], afr[mt], bfr[nt]);
        }
        __syncthreads();   // protect buf before it is refilled at kt+2
    }

    // epilogue
    #pragma unroll
    for (int mt = 0; mt < 4; ++mt) {
        int r = brow + wm + mt * 16 + (lane >> 2);
        #pragma unroll
        for (int nt = 0; nt < 4; ++nt) {
            int c = bcol + wn + nt * 8 + 2 * (lane & 3);
            if (c < N) {   // N even; c+1 also valid
                float v0 = acc[mt][nt][0], v1 = acc[mt][nt][1];
                float v2 = acc[mt][nt][2], v3 = acc[mt][nt][3];
                if (addC) {
                    v0 += C0[(size_t)r * N + c];
                    v1 += C0[(size_t)r * N + c + 1];
                    v2 += C0[(size_t)(r + 8) * N + c];
                    v3 += C0[(size_t)(r + 8) * N + c + 1];
                }
                C[(size_t)r * N + c] = v0;
                C[(size_t)r * N + c + 1] = v1;
                C[(size_t)(r + 8) * N + c] = v2;
                C[(size_t)(r + 8) * N + c + 1] = v3;
            }
        }
    }
}

// ---------------- RoPE (interleaved): q pe part in-place, ckv rope -> kpe ----
__global__ void rope_kernel(float* __restrict__ q, const float* __restrict__ ckv,
                            float* __restrict__ kpe,
                            const float* __restrict__ cosb, const float* __restrict__ sinb,
                            const int* __restrict__ pos) {
    int s = blockIdx.x;
    int p = pos[s];
    const float* c  = cosb + (size_t)p * ROPE;
    const float* sn = sinb + (size_t)p * ROPE;
    int idx = threadIdx.x;
    if (idx < NH * 32) {
        int h = idx >> 5, j = idx & 31;
        float* qp = q + (size_t)s * QDIM + h * QHD + NOPE;
        float x0 = qp[2 * j], x1 = qp[2 * j + 1];
        __syncwarp();
        qp[j]      = x0 * c[j]      - x1 * sn[j];
        qp[j + 32] = x1 * c[j + 32] + x0 * sn[j + 32];
    } else if (idx < NH * 32 + 32) {
        int j = idx - NH * 32;
        const float* kp = ckv + (size_t)s * CKV_N + KVLR;
        float x0 = kp[2 * j], x1 = kp[2 * j + 1];
        kpe[(size_t)s * ROPE + j]      = x0 * c[j]      - x1 * sn[j];
        kpe[(size_t)s * ROPE + j + 32] = x1 * c[j + 32] + x0 * sn[j + 32];
    }
}

// ---------------- Causal flash attention (fp32, online softmax) -------------
#define FBM 64
#define FBN 64
__global__ __launch_bounds__(256) void flash_kernel(
    const float* __restrict__ q, const float* __restrict__ kv,
    const float* __restrict__ kpe, float* __restrict__ attn) {
    __shared__ float Qs[16][FBM + 4];
    __shared__ float Ks[16][FBN + 4];
    __shared__ float Vs[16][VHD + 4];
    __shared__ float Ssm[FBM][FBN + 4];
    __shared__ float m_s[FBM], l_s[FBM], fac_s[FBM];

    int qbase = blockIdx.x * FBM;
    int h = blockIdx.y;
    int tid = threadIdx.x;
    int tx = tid & 15, ty = tid >> 4;

    float oacc[4][8];
    #pragma unroll
    for (int i = 0; i < 4; ++i)
        #pragma unroll
        for (int c = 0; c < 8; ++c) oacc[i][c] = 0.f;
    if (tid < FBM) { m_s[tid] = -1e30f; l_s[tid] = 0.f; }

    int qm = tid & 63;
    int qk = (tid >> 6) << 2;
    int vk = tid >> 4;
    int vc = (tid & 15) * 8;

    int srow = tid >> 2;       // softmax: 4 threads per row
    int sub  = tid & 3;

    int ntiles = (qbase / FBN) + 1;
    for (int jt = 0; jt < ntiles; ++jt) {
        int kbase = jt * FBN;
        float sacc[4][4];
        #pragma unroll
        for (int i = 0; i < 4; ++i)
            #pragma unroll
            for (int j = 0; j < 4; ++j) sacc[i][j] = 0.f;

        for (int kc = 0; kc < QHD; kc += 16) {
            __syncthreads();
            float4 qv = *(const float4*)(q + (size_t)(qbase + qm) * QDIM + h * QHD + kc + qk);
            Qs[qk + 0][qm] = qv.x; Qs[qk + 1][qm] = qv.y;
            Qs[qk + 2][qm] = qv.z; Qs[qk + 3][qm] = qv.w;
            float4 kvv;
            if (kc < NOPE)
                kvv = *(const float4*)(kv + (size_t)(kbase + qm) * KVDIM + h * (NOPE + VHD) + kc + qk);
            else
                kvv = *(const float4*)(kpe + (size_t)(kbase + qm) * ROPE + (kc - NOPE) + qk);
            Ks[qk + 0][qm] = kvv.x; Ks[qk + 1][qm] = kvv.y;
            Ks[qk + 2][qm] = kvv.z; Ks[qk + 3][qm] = kvv.w;
            __syncthreads();
            #pragma unroll
            for (int k = 0; k < 16; ++k) {
                float a[4], b[4];
                *(float4*)a = *(const float4*)&Qs[k][ty * 4];
                *(float4*)b = *(const float4*)&Ks[k][tx * 4];
                #pragma unroll
                for (int i = 0; i < 4; ++i)
                    #pragma unroll
                    for (int j = 0; j < 4; ++j)
                        sacc[i][j] = fmaf(a[i], b[j], sacc[i][j]);
            }
        }

        #pragma unroll
        for (int i = 0; i < 4; ++i) {
            int gr = qbase + ty * 4 + i;
            #pragma unroll
            for (int j = 0; j < 4; ++j) {
                int gc = kbase + tx * 4 + j;
                float v = sacc[i][j] * ATTN_SCALE;
                if (gc > gr) v = -1e30f;
                Ssm[ty * 4 + i][tx * 4 + j] = v;
            }
        }
        __syncthreads();

        // --- online softmax: 4 threads per row, shfl reduce ---
        {
            float mx = -1e30f;
            #pragma unroll
            for (int c = 0; c < 16; ++c) mx = fmaxf(mx, Ssm[srow][sub * 16 + c]);
            mx = fmaxf(mx, __shfl_xor_sync(0xffffffffu, mx, 1));
            mx = fmaxf(mx, __shfl_xor_sync(0xffffffffu, mx, 2));
            float mold = m_s[srow];
            float nm = fmaxf(mold, mx);
            float ps = 0.f;
            #pragma unroll
            for (int c = 0; c < 16; ++c) {
                float pv = __expf(Ssm[srow][sub * 16 + c] - nm);
                Ssm[srow][sub * 16 + c] = pv;
                ps += pv;
            }
            ps += __shfl_xor_sync(0xffffffffu, ps, 1);
            ps += __shfl_xor_sync(0xffffffffu, ps, 2);
            if (sub == 0) {
                float f = __expf(mold - nm);
                l_s[srow] = l_s[srow] * f + ps;
                m_s[srow] = nm;
                fac_s[srow] = f;
            }
        }
        __syncthreads();

        #pragma unroll
        for (int i = 0; i < 4; ++i) {
            float f = fac_s[ty * 4 + i];
            #pragma unroll
            for (int c = 0; c < 8; ++c) oacc[i][c] *= f;
        }

        for (int vcc = 0; vcc < FBN; vcc += 16) {
            __syncthreads();
            const float* vptr = kv + (size_t)(kbase + vcc + vk) * KVDIM + h * (NOPE + VHD) + NOPE + vc;
            *(float4*)&Vs[vk][vc]     = *(const float4*)(vptr);
            *(float4*)&Vs[vk][vc + 4] = *(const float4*)(vptr + 4);
            __syncthreads();
            #pragma unroll
            for (int k = 0; k < 16; ++k) {
                float b[8];
                *(float4*)(b)     = *(const float4*)&Vs[k][tx * 8];
                *(float4*)(b + 4) = *(const float4*)&Vs[k][tx * 8 + 4];
                #pragma unroll
                for (int i = 0; i < 4; ++i) {
                    float pv = Ssm[ty * 4 + i][vcc + k];
                    #pragma unroll
                    for (int c = 0; c < 8; ++c)
                        oacc[i][c] = fmaf(pv, b[c], oacc[i][c]);
                }
            }
        }
    }

    #pragma unroll
    for (int i = 0; i < 4; ++i) {
        int gr = qbase + ty * 4 + i;
        float inv = 1.f / l_s[ty * 4 + i];
        #pragma unroll
        for (int c = 0; c < 8; ++c)
            attn[(size_t)gr * H + h * VHD + tx * 8 + c] = oacc[i][c] * inv;
    }
}

// ---------------- SiLU(gate) * up, in place into gate -----------------------
__global__ void silu_mul_kernel(float* __restrict__ gate, const float* __restrict__ up, int n4) {
    int i = blockIdx.x * blockDim.x + threadIdx.x;
    if (i < n4) {
        float4 g = ((const float4*)gate)[i];
        float4 u = ((const float4*)up)[i];
        g.x = (g.x / (1.f + __expf(-g.x))) * u.x;
        g.y = (g.y / (1.f + __expf(-g.y))) * u.y;
        g.z = (g.z / (1.f + __expf(-g.z))) * u.z;
        g.w = (g.w / (1.f + __expf(-g.w))) * u.w;
        ((float4*)gate)[i] = g;
    }
}

// ---------------- Launch ----------------------------------------------------
static inline dim3 gemm_grid(int M, int N) {
    return dim3((N + BN - 1) / BN, (M + BM - 1) / BM);
}

extern "C" void kernel_launch(void* const* d_in, const int* in_sizes, int n_in,
                              void* d_out, int out_size) {
    const float* hs      = (const float*)d_in[0];
    const float* sinb    = (const float*)d_in[1];
    const float* cosb    = (const float*)d_in[2];
    const float* wq_a    = (const float*)d_in[3];
    const float* q_a_ln  = (const float*)d_in[4];
    const float* wq_b    = (const float*)d_in[5];
    const float* wkv_a   = (const float*)d_in[6];
    const float* kv_a_ln = (const float*)d_in[7];
    const float* wkv_b   = (const float*)d_in[8];
    const float* wo      = (const float*)d_in[9];
    const float* in_ln   = (const float*)d_in[10];
    const float* post_ln = (const float*)d_in[11];
    const float* w_gate  = (const float*)d_in[12];
    const float* w_up    = (const float*)d_in[13];
    const float* w_down  = (const float*)d_in[14];
    const int*   pos     = (const int*)d_in[15];
    float* out = (float*)d_out;

    float *x, *qlat, *qlatn, *qb, *ckv, *ckvn, *kvb, *kpe, *attn, *hidden, *y, *gate, *up;
    cudaGetSymbolAddress((void**)&x,      g_x);
    cudaGetSymbolAddress((void**)&qlat,   g_qlat);
    cudaGetSymbolAddress((void**)&qlatn,  g_qlatn);
    cudaGetSymbolAddress((void**)&qb,     g_q);
    cudaGetSymbolAddress((void**)&ckv,    g_ckv);
    cudaGetSymbolAddress((void**)&ckvn,   g_ckvn);
    cudaGetSymbolAddress((void**)&kvb,    g_kv);
    cudaGetSymbolAddress((void**)&kpe,    g_kpe);
    cudaGetSymbolAddress((void**)&attn,   g_attn);
    cudaGetSymbolAddress((void**)&hidden, g_hidden);
    cudaGetSymbolAddress((void**)&y,      g_y);
    cudaGetSymbolAddress((void**)&gate,   g_gate);
    cudaGetSymbolAddress((void**)&up,     g_up);

    // 1. x = rms(hidden_states, in_ln)
    rmsnorm_kernel<<<S, 256>>>(hs, in_ln, x, H, H, H);
    // 2. q_lat = x @ wq_a ; normalize ; q = q_lat_n @ wq_b
    tf32_gemm_kernel<<<gemm_grid(S, QLR), 256>>>(x, wq_a, nullptr, qlat, S, QLR, H, 0);
    rmsnorm_kernel<<<S, 256>>>(qlat, q_a_ln, qlatn, QLR, QLR, QLR);
    tf32_gemm_kernel<<<gemm_grid(S, QDIM), 256>>>(qlatn, wq_b, nullptr, qb, S, QDIM, QLR, 0);
    // 3. ckv = x @ wkv_a ; normalize first 512 ; kv = ckv_n @ wkv_b
    tf32_gemm_kernel<<<gemm_grid(S, CKV_N), 256>>>(x, wkv_a, nullptr, ckv, S, CKV_N, H, 0);
    rmsnorm_kernel<<<S, 256>>>(ckv, kv_a_ln, ckvn, KVLR, CKV_N, KVLR);
    tf32_gemm_kernel<<<gemm_grid(S, KVDIM), 256>>>(ckvn, wkv_b, nullptr, kvb, S, KVDIM, KVLR, 0);
    // 4. rope: q pe in place, k_pe -> kpe
    rope_kernel<<<S, 576>>>(qb, ckv, kpe, cosb, sinb, pos);
    // 5. causal attention -> attn [S, NH*128]
    flash_kernel<<<dim3(S / FBM, NH), 256>>>(qb, kvb, kpe, attn);
    // 6. hidden = hidden_states + attn @ wo
    tf32_gemm_kernel<<<gemm_grid(S, H), 256>>>(attn, wo, hs, hidden, S, H, H, 1);
    // 7. y = rms(hidden, post_ln)
    rmsnorm_kernel<<<S, 256>>>(hidden, post_ln, y, H, H, H);
    // 8. MLP
    tf32_gemm_kernel<<<gemm_grid(S, FF), 256>>>(y, w_gate, nullptr, gate, S, FF, H, 0);
    tf32_gemm_kernel<<<gemm_grid(S, FF), 256>>>(y, w_up, nullptr, up, S, FF, H, 0);
    int n4 = S * FF / 4;
    silu_mul_kernel<<<(n4 + 255) / 256, 256>>>(gate, up, n4);
    // 9. out = hidden + act @ w_down
    tf32_gemm_kernel<<<gemm_grid(S, H), 256>>>(gate, w_down, hidden, out, S, H, FF, 1);
}